// round 4
// baseline (speedup 1.0000x reference)
#include <cuda_runtime.h>
#include <math_constants.h>
#include <cstdint>

#define NPTS 16384
#define TILE 2048
#define LSZ  11          // keep top-11 including self, drop rank 0 (reference semantics)
#define FULLM 0xffffffffu

// Packed candidate data: x, y, z, sq  (sq computed with XLA-matching rounding)
__device__ float4 g_pc[2][NPTS];

__global__ void pack_kernel(const float* __restrict__ sc, const float* __restrict__ tc) {
    int j = blockIdx.x * blockDim.x + threadIdx.x;
    if (j >= NPTS) return;
    int cloud = blockIdx.y;
    const float* __restrict__ c = cloud ? tc : sc;
    float x = c[3 * j + 0];
    float y = c[3 * j + 1];
    float z = c[3 * j + 2];
    // XLA:GPU multi-row warp reduction for reduce-dim 3 (4 lanes/row, shfl-down
    // offsets 2 then 1) computes ((x*x + z*z) + y*y), each op rounded.
    float sq = __fadd_rn(__fadd_rn(__fmul_rn(x, x), __fmul_rn(z, z)), __fmul_rn(y, y));
    g_pc[cloud][j] = make_float4(x, y, z, sq);
}

__global__ __launch_bounds__(256) void knn_kernel(const float* __restrict__ src,
                                                  const float* __restrict__ tgt,
                                                  float* __restrict__ out) {
    __shared__ float4 smc[TILE];

    const int cloud = blockIdx.y;
    const int warp  = threadIdx.x >> 5;
    const int lane  = threadIdx.x & 31;
    const int iA = blockIdx.x * 16 + warp * 2;   // 8 warps * 2 points = 16 points per block
    const int iB = iA + 1;

    const float4* __restrict__ pc = g_pc[cloud];
    const float4 pA = pc[iA];
    const float4 pB = pc[iB];

    // Warp-distributed sorted lists (top-11 incl. self): lanes 0..10 = list A
    // (rank = lane), lanes 16..26 = list B (rank = lane-16).
    // (dist, idx) lexicographic ascending — matches top_k tie order.
    float ld = CUDART_INF_F;
    int   li = 0x7fffffff;
    float wdA = CUDART_INF_F, wdB = CUDART_INF_F;   // current worst (rank 10)
    int   wiA = 0x7fffffff,  wiB = 0x7fffffff;

    for (int t = 0; t < NPTS; t += TILE) {
        for (int s = threadIdx.x; s < TILE; s += 256)
            smc[s] = pc[t + s];
        __syncthreads();

        #pragma unroll 4
        for (int k = lane; k < TILE; k += 32) {
            float4 c = smc[k];
            int j = t + k;
            // dist = fl( fl(sq_i + sq_j) - 2*dot ),  dot = fma(z,z', fma(y,y', x*x'))
            float dotA = __fmaf_rn(pA.z, c.z, __fmaf_rn(pA.y, c.y, __fmul_rn(pA.x, c.x)));
            float dotB = __fmaf_rn(pB.z, c.z, __fmaf_rn(pB.y, c.y, __fmul_rn(pB.x, c.x)));
            float dA = __fmaf_rn(-2.0f, dotA, __fadd_rn(pA.w, c.w));
            float dB = __fmaf_rn(-2.0f, dotB, __fadd_rn(pB.w, c.w));

            unsigned mA = __ballot_sync(FULLM, dA <= wdA);
            unsigned mB = __ballot_sync(FULLM, dB <= wdB);
            int gbase = j - lane;

            while (mA) {   // mA warp-uniform
                int s = __ffs(mA) - 1; mA &= mA - 1;
                float dc = __shfl_sync(FULLM, dA, s);
                int   jc = gbase + s;
                if (dc < wdA || (dc == wdA && jc < wiA)) {   // uniform branch
                    unsigned bal = __ballot_sync(FULLM, (ld < dc) || (ld == dc && li < jc));
                    int pos = __popc(bal & 0x7FFu);
                    float sd = __shfl_up_sync(FULLM, ld, 1);
                    int   si = __shfl_up_sync(FULLM, li, 1);
                    if (lane < LSZ) {
                        if (lane == pos)      { ld = dc; li = jc; }
                        else if (lane > pos)  { ld = sd; li = si; }
                    }
                    wdA = __shfl_sync(FULLM, ld, LSZ - 1);
                    wiA = __shfl_sync(FULLM, li, LSZ - 1);
                }
            }
            while (mB) {
                int s = __ffs(mB) - 1; mB &= mB - 1;
                float dc = __shfl_sync(FULLM, dB, s);
                int   jc = gbase + s;
                if (dc < wdB || (dc == wdB && jc < wiB)) {
                    unsigned bal = __ballot_sync(FULLM, (ld < dc) || (ld == dc && li < jc));
                    int pos = __popc(bal & (0x7FFu << 16));
                    float sd = __shfl_up_sync(FULLM, ld, 1);
                    int   si = __shfl_up_sync(FULLM, li, 1);
                    int lin = lane - 16;
                    if (lane >= 16 && lane < 16 + LSZ) {
                        if (lin == pos)      { ld = dc; li = jc; }
                        else if (lin > pos)  { ld = sd; li = si; }
                    }
                    wdB = __shfl_sync(FULLM, ld, 16 + LSZ - 1);
                    wiB = __shfl_sync(FULLM, li, 16 + LSZ - 1);
                }
            }
        }
        __syncthreads();
    }

    // Epilogue: drop rank 0 (self). Rank r in 1..10 contributes
    // feats[idx_r, r-1]; M = max over the 10 kept ranks.
    const float* __restrict__ feats = cloud ? tgt : src;
    float v = -CUDART_INF_F;
    if (lane >= 1 && lane < LSZ)
        v = feats[(size_t)li * 64 + (lane - 1)];
    else if (lane >= 17 && lane < 16 + LSZ)
        v = feats[(size_t)li * 64 + (lane - 17)];
    #pragma unroll
    for (int m = 8; m; m >>= 1)
        v = fmaxf(v, __shfl_xor_sync(FULLM, v, m));   // half-warp reductions
    float maxA = __shfl_sync(FULLM, v, 0);
    float maxB = __shfl_sync(FULLM, v, 16);

    const float2* __restrict__ fA = (const float2*)(feats + (size_t)iA * 64);
    const float2* __restrict__ fB = (const float2*)(feats + (size_t)iB * 64);
    float2* oA = (float2*)(out + ((size_t)cloud * NPTS + iA) * 128);
    float2* oB = (float2*)(out + ((size_t)cloud * NPTS + iB) * 128);
    float2 a = fA[lane];
    float2 b = fB[lane];
    oA[lane] = a;
    oB[lane] = b;
    float2 da, db;
    da.x = __fsub_rn(maxA, a.x);  da.y = __fsub_rn(maxA, a.y);
    db.x = __fsub_rn(maxB, b.x);  db.y = __fsub_rn(maxB, b.y);
    oA[32 + lane] = da;
    oB[32 + lane] = db;
}

extern "C" void kernel_launch(void* const* d_in, const int* in_sizes, int n_in,
                              void* d_out, int out_size) {
    const float* src = (const float*)d_in[0];
    const float* tgt = (const float*)d_in[1];
    const float* sc  = (const float*)d_in[2];
    const float* tc  = (const float*)d_in[3];
    float* out = (float*)d_out;

    dim3 pg((NPTS + 255) / 256, 2);
    pack_kernel<<<pg, 256>>>(sc, tc);

    dim3 kg(NPTS / 16, 2);
    knn_kernel<<<kg, 256>>>(src, tgt, out);
}